// round 1
// baseline (speedup 1.0000x reference)
#include <cuda_runtime.h>
#include <math.h>

// Problem constants
#define BB      2
#define CIN_    64
#define LSEQ    4096            // H*W
#define NTOK    (BB*LSEQ)       // 8192
#define DM      64              // d_model
#define DI      128             // d_inner
#define DS      16              // d_state
#define DR      32              // dt_rank

// ---------------- device scratch (static, allocation-free) ----------------
__device__ float g_rgb  [NTOK*DM];
__device__ float g_dte  [NTOK*DM];
__device__ float g_xn   [NTOK*DM];
__device__ float g_xcpre[NTOK*DI];
__device__ float g_z    [NTOK*DI];
__device__ float g_O0   [NTOK*DM];
__device__ float g_O1   [NTOK*DM];
__device__ float g_h    [NTOK*DI*DS];   // 64 MB
__device__ float g_A    [DI*DS];

// ---------------- A = -exp(A_log) ----------------
__global__ void k_prep_A(const float* __restrict__ A_log) {
    int i = blockIdx.x * blockDim.x + threadIdx.x;
    if (i < DI*DS) g_A[i] = -expf(A_log[i]);
}

// ---------------- 1x1 conv, channel-major in -> token-major out ----------------
// in:  [B, CIN, L]   w: [DM, CIN]   out: [B*L, DM] (token-major)
__global__ __launch_bounds__(256) void k_conv_in(const float* __restrict__ in,
                                                 const float* __restrict__ w,
                                                 const float* __restrict__ bias,
                                                 float* __restrict__ out) {
    __shared__ float s_in[CIN_][65];
    __shared__ float s_w [DM][65];
    int bx  = blockIdx.x;
    int b   = bx >> 6;            // 64 tiles of 64 tokens per batch
    int l0  = (bx & 63) << 6;
    int tid = threadIdx.x;
    for (int i = tid; i < CIN_*64; i += 256) {
        int c = i >> 6, ll = i & 63;
        s_in[c][ll] = in[(b*CIN_ + c)*LSEQ + l0 + ll];
    }
    for (int i = tid; i < DM*CIN_; i += 256) {
        int o = i >> 6, c = i & 63;
        s_w[o][c] = w[i];
    }
    __syncthreads();
    int o  = tid & 63;            // lanes span o -> coalesced token-major writes
    int lg = tid >> 6;            // 4 groups of 16 l each
    for (int li = 0; li < 16; ++li) {
        int ll = lg*16 + li;
        float acc = bias[o];
        #pragma unroll 16
        for (int c = 0; c < CIN_; ++c) acc += s_w[o][c] * s_in[c][ll];
        out[(b*LSEQ + l0 + ll)*DM + o] = acc;
    }
}

// ---------------- final 1x1 conv, token-major in -> channel-major out ----------------
// in6: [B*L, DM]   w: [CIN, DM]   out: [B, CIN, L]
__global__ __launch_bounds__(256) void k_conv3(const float* __restrict__ in6,
                                               const float* __restrict__ w,
                                               const float* __restrict__ bias,
                                               float* __restrict__ out) {
    __shared__ float s_in[64][65];
    __shared__ float s_w [CIN_][65];
    int bx  = blockIdx.x;
    int b   = bx >> 6;
    int l0  = (bx & 63) << 6;
    int tid = threadIdx.x;
    for (int i = tid; i < 64*DM; i += 256) {
        int t = i >> 6, c = i & 63;
        s_in[t][c] = in6[(b*LSEQ + l0 + t)*DM + c];
    }
    for (int i = tid; i < CIN_*DM; i += 256) {
        int o = i >> 6, c = i & 63;
        s_w[o][c] = w[i];
    }
    __syncthreads();
    int t  = tid & 63;            // lanes span l -> coalesced channel-major writes
    int og = tid >> 6;
    for (int oi = 0; oi < 16; ++oi) {
        int o = og*16 + oi;
        float acc = bias[o];
        #pragma unroll 16
        for (int c = 0; c < DM; ++c) acc += s_w[o][c] * s_in[t][c];
        out[(b*CIN_ + o)*LSEQ + l0 + t] = acc;
    }
}

// ---------------- per-block phase A: acc -> rmsnorm -> in_proj (xz) ----------------
// 32 tokens / CTA, 256 threads.
__global__ __launch_bounds__(256) void k_block_a(const float* __restrict__ base,
                                                 const float* __restrict__ prev,
                                                 const float* __restrict__ norm_w,
                                                 const float* __restrict__ in_w) {
    __shared__ float s_x  [32][65];
    __shared__ float s_rms[32];
    __shared__ float s_xz [32][261];   // 261 % 32 == 5, coprime -> conflict-free
    int tok0 = blockIdx.x * 32;
    int tid  = threadIdx.x;

    for (int i = tid; i < 32*64; i += 256) {
        int t = i >> 6, c = i & 63;
        float v = base[(tok0 + t)*DM + c];
        if (prev) v += prev[(tok0 + t)*DM + c];
        s_x[t][c] = v;
    }
    __syncthreads();
    {   // rmsnorm reduction: 8 threads per token
        int t = tid >> 3, j = tid & 7;
        float s = 0.f;
        #pragma unroll
        for (int k = 0; k < 8; ++k) { float v = s_x[t][j + 8*k]; s += v*v; }
        s += __shfl_xor_sync(~0u, s, 4, 8);
        s += __shfl_xor_sync(~0u, s, 2, 8);
        s += __shfl_xor_sync(~0u, s, 1, 8);
        if (j == 0) s_rms[t] = rsqrtf(s * (1.0f/64.0f) + 1e-5f);
    }
    __syncthreads();
    for (int i = tid; i < 32*64; i += 256) {
        int t = i >> 6, c = i & 63;
        float v = s_x[t][c] * s_rms[t] * norm_w[c];
        s_x[t][c] = v;
        g_xn[(tok0 + t)*DM + c] = v;   // kept for the residual add in phase B
    }
    __syncthreads();

    // in_proj GEMV: lane = token, warp wj covers o = wj + 8*i
    int lane = tid & 31, wj = tid >> 5;
    float xr[64];
    #pragma unroll
    for (int c = 0; c < 64; ++c) xr[c] = s_x[lane][c];

    for (int i = 0; i < 32; i += 4) {
        int o0 = wj + 8*(i+0), o1 = wj + 8*(i+1), o2 = wj + 8*(i+2), o3 = wj + 8*(i+3);
        const float4* w0 = (const float4*)(in_w + o0*64);
        const float4* w1 = (const float4*)(in_w + o1*64);
        const float4* w2 = (const float4*)(in_w + o2*64);
        const float4* w3 = (const float4*)(in_w + o3*64);
        float a0 = 0.f, a1 = 0.f, a2 = 0.f, a3 = 0.f;
        #pragma unroll
        for (int k = 0; k < 16; ++k) {
            float4 v0 = w0[k], v1 = w1[k], v2 = w2[k], v3 = w3[k];
            float x0 = xr[4*k], x1 = xr[4*k+1], x2 = xr[4*k+2], x3 = xr[4*k+3];
            a0 += v0.x*x0 + v0.y*x1 + v0.z*x2 + v0.w*x3;
            a1 += v1.x*x0 + v1.y*x1 + v1.z*x2 + v1.w*x3;
            a2 += v2.x*x0 + v2.y*x1 + v2.z*x2 + v2.w*x3;
            a3 += v3.x*x0 + v3.y*x1 + v3.z*x2 + v3.w*x3;
        }
        s_xz[lane][o0] = a0; s_xz[lane][o1] = a1;
        s_xz[lane][o2] = a2; s_xz[lane][o3] = a3;
    }
    __syncthreads();
    // coalesced store of xc_pre / z
    for (int i = tid; i < 32*256; i += 256) {
        int t = i >> 8, o = i & 255;
        float v = s_xz[t][o];
        if (o < DI) g_xcpre[(tok0 + t)*DI + o]        = v;
        else        g_z    [(tok0 + t)*DI + (o - DI)] = v;
    }
}

// ---------------- per-block phase B: conv1d+SiLU, x_proj, dt_proj, SSM, gate, out_proj ----------------
// dynamic smem layout (floats):
//   s_xc  : 32*132  (float4-aligned rows)
//   s_ym  : 32*132
//   s_dl  : 32*129
//   s_dbc : 32*65
//   s_A   : 128*17
//   s_xn  : 32*65
#define SMB_XC   0
#define SMB_YM   (32*132)
#define SMB_DL   (SMB_YM + 32*132)
#define SMB_DBC  (SMB_DL + 32*129)
#define SMB_A    (SMB_DBC + 32*65)
#define SMB_XN   (SMB_A + 128*17)
#define SMB_TOT  (SMB_XN + 32*65)

__global__ __launch_bounds__(256) void k_block_b(
        const float* __restrict__ cw,  const float* __restrict__ cb,
        const float* __restrict__ xp_w,
        const float* __restrict__ dt_w, const float* __restrict__ dt_b,
        const float* __restrict__ Dp,
        const float* __restrict__ out_w,
        const float* __restrict__ h_in, float* __restrict__ h_out,
        float* __restrict__ out_cur) {
    extern __shared__ float sm[];
    float* s_xc  = sm + SMB_XC;
    float* s_ym  = sm + SMB_YM;
    float* s_dl  = sm + SMB_DL;
    float* s_dbc = sm + SMB_DBC;
    float* s_A   = sm + SMB_A;
    float* s_xn  = sm + SMB_XN;

    int tok0 = blockIdx.x * 32;
    int tid  = threadIdx.x;
    int l0   = tok0 & (LSEQ - 1);       // whole CTA is within one batch (4096 % 32 == 0)

    for (int i = tid; i < DI*DS; i += 256) { int d = i >> 4, s = i & 15; s_A[d*17 + s] = g_A[i]; }
    for (int i = tid; i < 32*64; i += 256) { int t = i >> 6, c = i & 63; s_xn[t*65 + c] = g_xn[(tok0 + t)*DM + c]; }

    // depthwise conv (taps l-1,l,l+1, zero pad at batch edges) + SiLU
    for (int i = tid; i < 32*DI; i += 256) {
        int t = i >> 7, d = i & 127;
        int l = l0 + t;
        int idx = (tok0 + t)*DI + d;
        float v = cb[d] + cw[d*3 + 1] * g_xcpre[idx];
        if (l > 0)        v += cw[d*3 + 0] * g_xcpre[idx - DI];
        if (l < LSEQ - 1) v += cw[d*3 + 2] * g_xcpre[idx + DI];
        v = v / (1.0f + __expf(-v));
        s_xc[t*132 + d] = v;
    }
    __syncthreads();

    int lane = tid & 31, wj = tid >> 5;

    // x_proj GEMV: 64 outputs, warp wj handles 8
    {
        const float4* xrow = (const float4*)(s_xc + lane*132);
        float a[8]; 
        #pragma unroll
        for (int oi = 0; oi < 8; ++oi) a[oi] = 0.f;
        #pragma unroll 8
        for (int c4 = 0; c4 < 32; ++c4) {
            float4 xv = xrow[c4];
            #pragma unroll
            for (int oi = 0; oi < 8; ++oi) {
                float4 wv = *(const float4*)(xp_w + (wj*8 + oi)*DI + 4*c4);
                a[oi] += wv.x*xv.x + wv.y*xv.y + wv.z*xv.z + wv.w*xv.w;
            }
        }
        #pragma unroll
        for (int oi = 0; oi < 8; ++oi) s_dbc[lane*65 + wj*8 + oi] = a[oi];
    }
    __syncthreads();

    // dt_proj + softplus
    {
        float din[DR];
        #pragma unroll
        for (int r = 0; r < DR; ++r) din[r] = s_dbc[lane*65 + r];
        #pragma unroll 2
        for (int oi = 0; oi < 16; ++oi) {
            int o = wj*16 + oi;
            const float4* wr = (const float4*)(dt_w + o*DR);
            float a = dt_b[o];
            #pragma unroll
            for (int r4 = 0; r4 < 8; ++r4) {
                float4 wv = wr[r4];
                a += wv.x*din[4*r4] + wv.y*din[4*r4+1] + wv.z*din[4*r4+2] + wv.w*din[4*r4+3];
            }
            float sp = fmaxf(a, 0.f) + log1pf(__expf(-fabsf(a)));
            s_dl[lane*129 + o] = sp;
        }
    }
    __syncthreads();

    // SSM state update + y + gating
    for (int i = tid; i < 32*DI; i += 256) {
        int t = i >> 7, d = i & 127;
        float dl  = s_dl[t*129 + d];
        float xcv = s_xc[t*132 + d];
        float dx  = dl * xcv;
        size_t hbase = ((size_t)(tok0 + t)*DI + d) * DS;
        float h[DS];
        if (h_in) {
            #pragma unroll
            for (int q = 0; q < 4; ++q) {
                float4 hv = *((const float4*)(h_in + hbase) + q);
                h[4*q] = hv.x; h[4*q+1] = hv.y; h[4*q+2] = hv.z; h[4*q+3] = hv.w;
            }
        } else {
            #pragma unroll
            for (int s = 0; s < DS; ++s) h[s] = 0.f;
        }
        float y = 0.f;
        #pragma unroll
        for (int s = 0; s < DS; ++s) {
            float dA = __expf(dl * s_A[d*17 + s]);
            float hn = dA * h[s] + dx * s_dbc[t*65 + 32 + s];
            h[s] = hn;
            y += hn * s_dbc[t*65 + 48 + s];
        }
        #pragma unroll
        for (int q = 0; q < 4; ++q)
            *((float4*)(h_out + hbase) + q) = make_float4(h[4*q], h[4*q+1], h[4*q+2], h[4*q+3]);
        y += __ldg(&Dp[d]) * xcv;
        float z  = g_z[(tok0 + t)*DI + d];
        float sz = z / (1.0f + __expf(-z));
        s_ym[t*132 + d] = y * sz;
    }
    __syncthreads();

    // out_proj GEMV + residual(xn); stage into s_dbc (B/C dead now)
    {
        const float4* yrow = (const float4*)(s_ym + lane*132);
        float a[8];
        #pragma unroll
        for (int oi = 0; oi < 8; ++oi) a[oi] = 0.f;
        #pragma unroll 8
        for (int c4 = 0; c4 < 32; ++c4) {
            float4 yv = yrow[c4];
            #pragma unroll
            for (int oi = 0; oi < 8; ++oi) {
                float4 wv = *(const float4*)(out_w + (wj*8 + oi)*DI + 4*c4);
                a[oi] += wv.x*yv.x + wv.y*yv.y + wv.z*yv.z + wv.w*yv.w;
            }
        }
        #pragma unroll
        for (int oi = 0; oi < 8; ++oi) {
            int o = wj*8 + oi;
            s_dbc[lane*65 + o] = a[oi] + s_xn[lane*65 + o];
        }
    }
    __syncthreads();
    for (int i = tid; i < 32*64; i += 256) {
        int t = i >> 6, o = i & 63;
        out_cur[(tok0 + t)*DM + o] = s_dbc[t*65 + o];
    }
}

// ---------------- host launch ----------------
extern "C" void kernel_launch(void* const* d_in, const int* in_sizes, int n_in,
                              void* d_out, int out_size) {
    const float* rgb    = (const float*)d_in[0];
    const float* dte    = (const float*)d_in[1];
    const float* c1w    = (const float*)d_in[2];
    const float* c1b    = (const float*)d_in[3];
    const float* c2w    = (const float*)d_in[4];
    const float* c2b    = (const float*)d_in[5];
    const float* c3w    = (const float*)d_in[6];
    const float* c3b    = (const float*)d_in[7];
    const float* normw  = (const float*)d_in[8];
    const float* inw    = (const float*)d_in[9];
    const float* convw  = (const float*)d_in[10];
    const float* convb  = (const float*)d_in[11];
    const float* xpw    = (const float*)d_in[12];
    const float* dtw    = (const float*)d_in[13];
    const float* dtb    = (const float*)d_in[14];
    const float* A_log  = (const float*)d_in[15];
    const float* Dpp    = (const float*)d_in[16];
    const float* outw   = (const float*)d_in[17];
    float* out = (float*)d_out;

    float *p_rgb, *p_dte, *p_O0, *p_O1, *p_h;
    cudaGetSymbolAddress((void**)&p_rgb, g_rgb);
    cudaGetSymbolAddress((void**)&p_dte, g_dte);
    cudaGetSymbolAddress((void**)&p_O0,  g_O0);
    cudaGetSymbolAddress((void**)&p_O1,  g_O1);
    cudaGetSymbolAddress((void**)&p_h,   g_h);

    const int smemB = SMB_TOT * (int)sizeof(float);
    cudaFuncSetAttribute(k_block_b, cudaFuncAttributeMaxDynamicSharedMemorySize, smemB);

    // h part of the output lives right after the conv3 output, if present
    const int conv_elems = BB*CIN_*LSEQ;                 // 524288
    const int h_elems    = NTOK*DI*DS;                   // 16777216
    float* h_final = (out_size >= conv_elems + h_elems) ? (out + conv_elems) : p_h;

    k_prep_A<<<(DI*DS + 255)/256, 256>>>(A_log);
    k_conv_in<<<BB*LSEQ/64, 256>>>(rgb, c1w, c1b, p_rgb);
    k_conv_in<<<BB*LSEQ/64, 256>>>(dte, c2w, c2b, p_dte);

    const float* bases[6] = { p_rgb, p_dte, p_rgb, p_dte, p_rgb, p_dte };
    float* outs[2] = { p_O0, p_O1 };
    const float* prev = nullptr;
    for (int k = 0; k < 6; ++k) {
        k_block_a<<<NTOK/32, 256>>>(bases[k], prev, normw, inw);
        const float* h_in = (k == 0) ? nullptr : p_h;
        float* h_o        = (k == 5) ? h_final : p_h;
        k_block_b<<<NTOK/32, 256, smemB>>>(convw, convb, xpw, dtw, dtb, Dpp, outw,
                                           h_in, h_o, outs[k & 1]);
        prev = outs[k & 1];
    }
    k_conv3<<<BB*LSEQ/64, 256>>>(prev, c3w, c3b, out);
}